// round 16
// baseline (speedup 1.0000x reference)
#include <cuda_runtime.h>
#include <math_constants.h>

#define BB 256
#define SS 4096
#define HH 128
#define SPLIT 4
#define ROWS_PER_CTA (SS / SPLIT)    // 1024
#define NWARP 8
#define NTHREADS (NWARP * 32)        // 256
#define ROWS_PER_ITER (NWARP * 2)    // 16 rows per CTA iteration
#define ITERS (ROWS_PER_CTA / ROWS_PER_ITER) // 64

// Scratch for split partials: per (batch, split): [L, ctx[128], pad]
// No max-tracking needed: scores are bounded (~|p| < 40 at 18+ sigma), so raw
// exp(p) stays far inside fp32 range and partials combine by plain summation.
__device__ float g_partial[BB * SPLIT * (HH + 2)];
__device__ int   g_count[BB];   // zero-initialized; reset by last CTA each launch

// Hardware tanh approximation (MUFU.TANH): 1 MUFU op per element.
__device__ __forceinline__ float tanh_hw(float x) {
    float y;
    asm("tanh.approx.f32 %0, %1;" : "=f"(y) : "f"(x));
    return y;
}

// Read-only 128-bit load with 256B L2 fetch-granularity hint: fewer, larger
// LTS transactions for this perfectly-contiguous stream.
__device__ __forceinline__ float4 ldg_v4_L2_256(const float4* p) {
    float4 v;
    asm volatile("ld.global.nc.L2::256B.v4.f32 {%0, %1, %2, %3}, [%4];"
                 : "=f"(v.x), "=f"(v.y), "=f"(v.z), "=f"(v.w)
                 : "l"(p));
    return v;
}

// grid supplies only 6.92 CTAs/SM -> min-blocks 7 keeps full residency; the
// whole 1024-CTA grid is co-resident in a single wave (no wave boundary).
__global__ __launch_bounds__(NTHREADS, 7)
void attn_fused(const float* __restrict__ x, const float* __restrict__ w,
                float* __restrict__ out) {
    const int blk   = blockIdx.x;
    const int batch = blk / SPLIT;
    const int split = blk % SPLIT;
    const int warp  = threadIdx.x >> 5;
    const int lane  = threadIdx.x & 31;

    // attention weights: 4 per thread, held in registers
    const float4 w4 = __ldg(reinterpret_cast<const float4*>(w) + lane);

    const float* xb = x + (size_t)batch * SS * HH + (size_t)split * ROWS_PER_CTA * HH;

    float l = 0.0f;
    float accx = 0.0f, accy = 0.0f, accz = 0.0f, accw = 0.0f;

    #pragma unroll 8
    for (int i = 0; i < ITERS; ++i) {
        // two rows per warp per iteration -> two independent MUFU/SHFL chains.
        // Warps interleave rows so the CTA sweeps a contiguous window each
        // step (best DRAM page locality, per R14 experiment).
        const int s0 = (warp * 2)     + i * ROWS_PER_ITER;
        const int s1 = (warp * 2 + 1) + i * ROWS_PER_ITER;
        const float4 v0 = ldg_v4_L2_256(reinterpret_cast<const float4*>(xb + (size_t)s0 * HH) + lane);
        const float4 v1 = ldg_v4_L2_256(reinterpret_cast<const float4*>(xb + (size_t)s1 * HH) + lane);

        float p0 = tanh_hw(v0.x) * w4.x;
        float p1 = tanh_hw(v1.x) * w4.x;
        p0 = fmaf(tanh_hw(v0.y), w4.y, p0);
        p1 = fmaf(tanh_hw(v1.y), w4.y, p1);
        p0 = fmaf(tanh_hw(v0.z), w4.z, p0);
        p1 = fmaf(tanh_hw(v1.z), w4.z, p1);
        p0 = fmaf(tanh_hw(v0.w), w4.w, p0);
        p1 = fmaf(tanh_hw(v1.w), w4.w, p1);

        // two interleaved butterfly reductions (independent chains pipeline)
        #pragma unroll
        for (int off = 16; off; off >>= 1) {
            p0 += __shfl_xor_sync(0xffffffffu, p0, off);
            p1 += __shfl_xor_sync(0xffffffffu, p1, off);
        }

        // branchless softmax accumulation: raw exp, no running max.
        const float e0 = __expf(p0);
        const float e1 = __expf(p1);
        l   += e0 + e1;
        accx = fmaf(e0, v0.x, fmaf(e1, v1.x, accx));
        accy = fmaf(e0, v0.y, fmaf(e1, v1.y, accy));
        accz = fmaf(e0, v0.z, fmaf(e1, v1.z, accz));
        accw = fmaf(e0, v0.w, fmaf(e1, v1.w, accw));
    }

    // ---- CTA combine across 8 warps (plain sums) ----
    __shared__ float sm_l[NWARP];
    __shared__ float4 sm_acc[NWARP][32];   // [warp][lane] = this thread's 4 h-values

    if (lane == 0) sm_l[warp] = l;
    sm_acc[warp][lane] = make_float4(accx, accy, accz, accw);
    __syncthreads();

    if (threadIdx.x < HH) {
        const int h = threadIdx.x;
        const float* accf = reinterpret_cast<const float*>(sm_acc);
        float L = 0.0f, C = 0.0f;
        #pragma unroll
        for (int ww = 0; ww < NWARP; ++ww) {
            L += sm_l[ww];
            C += accf[ww * HH + h];
        }

        float* o = g_partial + (size_t)blk * (HH + 2);
        if (h == 0) o[0] = L;
        o[1 + h] = C;
    }

    // ---- last CTA of this batch combines the SPLIT partials (fused pass2) ----
    __shared__ int s_last;
    __syncthreads();
    if (threadIdx.x == 0) {
        __threadfence();   // make this CTA's partial visible before signaling
        const int prev = atomicAdd(&g_count[batch], 1);
        s_last = (prev == SPLIT - 1) ? 1 : 0;
    }
    __syncthreads();

    if (s_last) {
        if (threadIdx.x < HH) {
            const int h = threadIdx.x;
            volatile const float* base =
                g_partial + (size_t)batch * SPLIT * (HH + 2);

            float L = 0.0f, C = 0.0f;
            #pragma unroll
            for (int k = 0; k < SPLIT; ++k) {
                volatile const float* pk = base + (size_t)k * (HH + 2);
                L += pk[0];
                C += pk[1 + h];
            }
            out[(size_t)batch * HH + h] = C / L;
        }
        if (threadIdx.x == 0) g_count[batch] = 0;   // reset for next graph replay
    }
}

extern "C" void kernel_launch(void* const* d_in, const int* in_sizes, int n_in,
                              void* d_out, int out_size) {
    const float* x = (const float*)d_in[0];   // [B, S, H] fp32
    const float* w = (const float*)d_in[1];   // [H, 1]    fp32
    float* out = (float*)d_out;               // [B, H]    fp32

    attn_fused<<<BB * SPLIT, NTHREADS>>>(x, w, out);
}

// round 17
// speedup vs baseline: 1.0133x; 1.0133x over previous
#include <cuda_runtime.h>
#include <math_constants.h>

#define BB 256
#define SS 4096
#define HH 128
#define SPLIT 4
#define ROWS_PER_CTA (SS / SPLIT)    // 1024
#define NWARP 8
#define NTHREADS (NWARP * 32)        // 256
#define ROWS_PER_ITER (NWARP * 2)    // 16 rows per CTA iteration
#define ITERS (ROWS_PER_CTA / ROWS_PER_ITER) // 64

// Scratch for split partials: per (batch, split): [L, ctx[128], pad]
// No max-tracking needed: scores are bounded (~|p| < 40 at 18+ sigma), so raw
// exp(p) stays far inside fp32 range and partials combine by plain summation.
__device__ float g_partial[BB * SPLIT * (HH + 2)];
__device__ int   g_count[BB];   // zero-initialized; reset by last CTA each launch

// Hardware tanh approximation (MUFU.TANH): 1 MUFU op per element.
__device__ __forceinline__ float tanh_hw(float x) {
    float y;
    asm("tanh.approx.f32 %0, %1;" : "=f"(y) : "f"(x));
    return y;
}

// grid supplies only 6.92 CTAs/SM -> min-blocks 7 keeps full residency; the
// whole 1024-CTA grid is co-resident in a single wave (no wave boundary).
__global__ __launch_bounds__(NTHREADS, 7)
void attn_fused(const float* __restrict__ x, const float* __restrict__ w,
                float* __restrict__ out) {
    const int blk   = blockIdx.x;
    const int batch = blk / SPLIT;
    const int split = blk % SPLIT;
    const int warp  = threadIdx.x >> 5;
    const int lane  = threadIdx.x & 31;

    // attention weights: 4 per thread, held in registers
    const float4 w4 = __ldg(reinterpret_cast<const float4*>(w) + lane);

    const float* xb = x + (size_t)batch * SS * HH + (size_t)split * ROWS_PER_CTA * HH;

    float l = 0.0f;
    float accx = 0.0f, accy = 0.0f, accz = 0.0f, accw = 0.0f;

    #pragma unroll 8
    for (int i = 0; i < ITERS; ++i) {
        // two rows per warp per iteration -> two independent MUFU/SHFL chains.
        // Warps interleave rows so the CTA sweeps a contiguous window each
        // step (best DRAM page locality, per R14 experiment).
        // __ldcs: streamed once, evict-first (no L1 reuse exists).
        const int s0 = (warp * 2)     + i * ROWS_PER_ITER;
        const int s1 = (warp * 2 + 1) + i * ROWS_PER_ITER;
        const float4 v0 = __ldcs(reinterpret_cast<const float4*>(xb + (size_t)s0 * HH) + lane);
        const float4 v1 = __ldcs(reinterpret_cast<const float4*>(xb + (size_t)s1 * HH) + lane);

        float p0 = tanh_hw(v0.x) * w4.x;
        float p1 = tanh_hw(v1.x) * w4.x;
        p0 = fmaf(tanh_hw(v0.y), w4.y, p0);
        p1 = fmaf(tanh_hw(v1.y), w4.y, p1);
        p0 = fmaf(tanh_hw(v0.z), w4.z, p0);
        p1 = fmaf(tanh_hw(v1.z), w4.z, p1);
        p0 = fmaf(tanh_hw(v0.w), w4.w, p0);
        p1 = fmaf(tanh_hw(v1.w), w4.w, p1);

        // two interleaved butterfly reductions (independent chains pipeline)
        #pragma unroll
        for (int off = 16; off; off >>= 1) {
            p0 += __shfl_xor_sync(0xffffffffu, p0, off);
            p1 += __shfl_xor_sync(0xffffffffu, p1, off);
        }

        // branchless softmax accumulation: raw exp, no running max.
        const float e0 = __expf(p0);
        const float e1 = __expf(p1);
        l   += e0 + e1;
        accx = fmaf(e0, v0.x, fmaf(e1, v1.x, accx));
        accy = fmaf(e0, v0.y, fmaf(e1, v1.y, accy));
        accz = fmaf(e0, v0.z, fmaf(e1, v1.z, accz));
        accw = fmaf(e0, v0.w, fmaf(e1, v1.w, accw));
    }

    // ---- CTA combine across 8 warps (plain sums) ----
    __shared__ float sm_l[NWARP];
    __shared__ float4 sm_acc[NWARP][32];   // [warp][lane] = this thread's 4 h-values

    if (lane == 0) sm_l[warp] = l;
    sm_acc[warp][lane] = make_float4(accx, accy, accz, accw);
    __syncthreads();

    if (threadIdx.x < HH) {
        const int h = threadIdx.x;
        const float* accf = reinterpret_cast<const float*>(sm_acc);
        float L = 0.0f, C = 0.0f;
        #pragma unroll
        for (int ww = 0; ww < NWARP; ++ww) {
            L += sm_l[ww];
            C += accf[ww * HH + h];
        }

        float* o = g_partial + (size_t)blk * (HH + 2);
        if (h == 0) o[0] = L;
        o[1 + h] = C;
    }

    // ---- last CTA of this batch combines the SPLIT partials (fused pass2) ----
    __shared__ int s_last;
    __syncthreads();
    if (threadIdx.x == 0) {
        __threadfence();   // make this CTA's partial visible before signaling
        const int prev = atomicAdd(&g_count[batch], 1);
        s_last = (prev == SPLIT - 1) ? 1 : 0;
    }
    __syncthreads();

    if (s_last) {
        if (threadIdx.x < HH) {
            const int h = threadIdx.x;
            volatile const float* base =
                g_partial + (size_t)batch * SPLIT * (HH + 2);

            float L = 0.0f, C = 0.0f;
            #pragma unroll
            for (int k = 0; k < SPLIT; ++k) {
                volatile const float* pk = base + (size_t)k * (HH + 2);
                L += pk[0];
                C += pk[1 + h];
            }
            out[(size_t)batch * HH + h] = C / L;
        }
        if (threadIdx.x == 0) g_count[batch] = 0;   // reset for next graph replay
    }
}

extern "C" void kernel_launch(void* const* d_in, const int* in_sizes, int n_in,
                              void* d_out, int out_size) {
    const float* x = (const float*)d_in[0];   // [B, S, H] fp32
    const float* w = (const float*)d_in[1];   // [H, 1]    fp32
    float* out = (float*)d_out;               // [B, H]    fp32

    attn_fused<<<BB * SPLIT, NTHREADS>>>(x, w, out);
}